// round 15
// baseline (speedup 1.0000x reference)
#include <cuda_runtime.h>
#include <cstdint>

#define PB 2
#define PS 2048
#define PE 1024
#define PH 16
#define PHD 64
#define MROWS (PB * PS * PH)
#define PAD 68   // qkv internal tiles

// Scratch, tf32 bit patterns (allocation-free rule).
// g_Q: A-frag layout  [bh][qt 16][kc 8][rc 8][lane 32][4]
// g_K: B-frag layout  [bh][kt 64][kc 8][nc 4][lane 32][2]
// g_V: B-frag layout  [bh][vt 64][kchunk 4][nc 8][lane 32][2]
// g_Y: A-frag layout  [mt 32][kc 128][rc 8][lane 32][4]
// g_Wp: B-frag layout [nt 8][kc 128][nc 16][lane 32][2]
__device__ uint32_t g_Q[(size_t)PB * PH * PS * PHD];
__device__ uint32_t g_K[(size_t)PB * PH * PS * PHD];
__device__ uint32_t g_V[(size_t)PB * PH * PS * PHD];
__device__ uint32_t g_Y[(size_t)PB * PS * PE];
__device__ uint32_t g_Wp[(size_t)PE * PE];

__device__ __forceinline__ uint32_t f2tf(float x) {
  uint32_t u;
  asm("cvt.rna.tf32.f32 %0, %1;" : "=r"(u) : "f"(x));
  return u;
}
__device__ __forceinline__ float ex2(float x) {
  float y;
  asm("ex2.approx.ftz.f32 %0, %1;" : "=f"(y) : "f"(x));
  return y;
}
__device__ __forceinline__ void mma_tf32(float c[4], uint32_t a0, uint32_t a1,
                                         uint32_t a2, uint32_t a3, uint32_t b0,
                                         uint32_t b1) {
  asm volatile(
      "mma.sync.aligned.m16n8k8.row.col.f32.tf32.tf32.f32 "
      "{%0,%1,%2,%3}, {%4,%5,%6,%7}, {%8,%9}, {%0,%1,%2,%3};"
      : "+f"(c[0]), "+f"(c[1]), "+f"(c[2]), "+f"(c[3])
      : "r"(a0), "r"(a1), "r"(a2), "r"(a3), "r"(b0), "r"(b1));
}
__device__ __forceinline__ void cpa16(uint32_t* smem_dst, const void* gsrc) {
  uint32_t d = (uint32_t)__cvta_generic_to_shared(smem_dst);
  asm volatile("cp.async.cg.shared.global [%0], [%1], 16;" ::"r"(d), "l"(gsrc));
}
__device__ __forceinline__ void cp_commit() {
  asm volatile("cp.async.commit_group;");
}
__device__ __forceinline__ void cp_wait0() {
  asm volatile("cp.async.wait_group 0;");
}

// A-frag index within one [kc][rc][lane][4] tile set, RCN row-chunks tall.
__device__ __forceinline__ size_t aidx(int row, int col, int RCN) {
  int rc = row >> 4, jlo = (row >> 3) & 1, g = row & 7;
  int kc = col >> 3, t = col & 3, hi = (col >> 2) & 1;
  return ((size_t)(kc * RCN + rc) * 32 + g * 4 + t) * 4 + hi * 2 + jlo;
}
// B-frag index within one [kc][nc][lane][2] tile set, NCN col-chunks wide.
__device__ __forceinline__ size_t bidx(int n, int k, int NCN) {
  int nc = n >> 3, g = n & 7;
  int kc = k >> 3, t = k & 3, hi = (k >> 2) & 1;
  return ((size_t)(kc * NCN + nc) * 32 + g * 4 + t) * 2 + hi;
}

// ---------------------------------------------------------------------------
// Kernel 1: fused QKV projection + (extra blocks) Wp fragment conversion.
// Compute blocks [0,512): bid = (bh 32, qt 16); 128 consecutive s of ONE head.
// Epilogue converts C-frags to A/B-frag register order via quad/cross-quad
// shuffles -> Q stored as STG.128, K/V as STG.64, all warp-contiguous.
// Blocks [512,768): convert Wp, 8 k per thread -> 2 contiguous STG.128.
// ---------------------------------------------------------------------------
__global__ __launch_bounds__(512) void qkv_kernel(
    const float* __restrict__ x,
    const float* __restrict__ Wq, const float* __restrict__ Wk,
    const float* __restrict__ Wv, const float* __restrict__ Wp,
    const float* __restrict__ bq, const float* __restrict__ bk,
    const float* __restrict__ bv) {
  const int tid = threadIdx.x;

  if (blockIdx.x >= 512) {  // Wp conversion: one n, 8 k per thread
    int p = (blockIdx.x - 512) * 512 + tid;  // 0..131071
    int n = p & 1023, kg = p >> 10;          // kg = k-chunk (8 wide)
    const float* src = &Wp[(size_t)n * 1024 + kg * 8];
    float4 w0 = *(const float4*)src;
    float4 w1 = *(const float4*)(src + 4);
    uint4 ua = {f2tf(w0.x), f2tf(w1.x), f2tf(w0.y), f2tf(w1.y)};
    uint4 ub = {f2tf(w0.z), f2tf(w1.z), f2tf(w0.w), f2tf(w1.w)};
    size_t o = (size_t)(n >> 7) * 131072 + (size_t)kg * 1024 +
               ((n >> 3) & 15) * 64 + (n & 7) * 8;
    *(uint4*)&g_Wp[o] = ua;
    *(uint4*)&g_Wp[o + 4] = ub;
    return;
  }

  extern __shared__ uint32_t sm[];
  uint32_t* Xs = sm;               // 128*PAD
  uint32_t* Aq = Xs + 128 * PAD;   // 64*PAD each
  uint32_t* Ak = Aq + 64 * PAD;
  uint32_t* Av = Ak + 64 * PAD;
  const int qt = blockIdx.x & 15, bh = blockIdx.x >> 4;
  const int b = bh >> 4, h = bh & 15;
  const int s0 = qt * 128;

#pragma unroll
  for (int r = 0; r < 2; r++) {
    int f = tid + 512 * r;
    int row = f >> 4, col = (f & 15) * 4;
    float4 q4 = *(const float4*)&Wq[row * 64 + col];
    float4 k4 = *(const float4*)&Wk[row * 64 + col];
    float4 v4 = *(const float4*)&Wv[row * 64 + col];
    uint4 uq = {f2tf(q4.x), f2tf(q4.y), f2tf(q4.z), f2tf(q4.w)};
    uint4 uk = {f2tf(k4.x), f2tf(k4.y), f2tf(k4.z), f2tf(k4.w)};
    uint4 uv = {f2tf(v4.x), f2tf(v4.y), f2tf(v4.z), f2tf(v4.w)};
    *(uint4*)&Aq[row * PAD + col] = uq;
    *(uint4*)&Ak[row * PAD + col] = uk;
    *(uint4*)&Av[row * PAD + col] = uv;
  }
#pragma unroll
  for (int r = 0; r < 4; r++) {
    int f = tid + 512 * r;
    int row = f >> 4, col = (f & 15) * 4;
    size_t xoff = ((size_t)((b * PS + s0 + row) * PH + h)) * 64 + col;
    float4 v = *(const float4*)&x[xoff];
    uint4 u = {f2tf(v.x), f2tf(v.y), f2tf(v.z), f2tf(v.w)};
    *(uint4*)&Xs[row * PAD + col] = u;
  }
  __syncthreads();

  const int wid = tid >> 5, lane = tid & 31;
  const int g = lane >> 2, t = lane & 3;
  const int mrow = (wid & 7) * 16;
  const int wn = wid >> 3;

  float cq[4][4] = {}, ck[4][4] = {}, cv[4][4] = {};
#pragma unroll
  for (int k0 = 0; k0 < 64; k0 += 8) {
    uint32_t a0 = Xs[(mrow + g) * PAD + k0 + t];
    uint32_t a1 = Xs[(mrow + g + 8) * PAD + k0 + t];
    uint32_t a2 = Xs[(mrow + g) * PAD + k0 + t + 4];
    uint32_t a3 = Xs[(mrow + g + 8) * PAD + k0 + t + 4];
#pragma unroll
    for (int nt = 0; nt < 4; nt++) {
      int n0 = wn * 32 + nt * 8;
      mma_tf32(cq[nt], a0, a1, a2, a3, Aq[(n0 + g) * PAD + k0 + t],
               Aq[(n0 + g) * PAD + k0 + t + 4]);
      mma_tf32(ck[nt], a0, a1, a2, a3, Ak[(n0 + g) * PAD + k0 + t],
               Ak[(n0 + g) * PAD + k0 + t + 4]);
      mma_tf32(cv[nt], a0, a1, a2, a3, Av[(n0 + g) * PAD + k0 + t],
               Av[(n0 + g) * PAD + k0 + t + 4]);
    }
  }

  const float qscale = 0.125f * 1.4426950408889634f;  // 1/sqrt(64) * log2(e)
  const size_t qbase = (size_t)(bh * 16 + qt) * 8192;
  const size_t kvb = (size_t)(bh * 64 + qt * 4) * 2048 +
                     (size_t)(mrow >> 5) * 2048;  // this warp's 32-row kt tile
  const int rc = wid & 7;
  const int nc0 = (mrow & 31) >> 3;  // 0 or 2
  const int src0 = (lane & ~3) + (t >> 1), src1 = src0 + 2;
  const bool odd = t & 1;
  const int srcV0 = (lane & 3) * 4 + (lane >> 3);  // V cross-quad sources
  const int srcV1 = srcV0 + 16;
  const bool selv = (lane >> 2) & 1;

#pragma unroll
  for (int nt = 0; nt < 4; nt++) {
    const int kcol = wn * 4 + nt;  // k-chunk of cols kcol*8..+7
    uint32_t vq[4], vk[4], vv[4];
#pragma unroll
    for (int i = 0; i < 4; i++) {
      int col = kcol * 8 + 2 * t + (i & 1);
      vq[i] = f2tf((cq[nt][i] + bq[col]) * qscale);
      vk[i] = f2tf(ck[nt][i] + bk[col]);
      vv[i] = f2tf(cv[nt][i] + bv[col]);
    }
    // Q: C-frag -> A-frag via quad shuffles, one STG.128
    {
      uint32_t x00 = __shfl_sync(~0u, vq[0], src0);
      uint32_t x01 = __shfl_sync(~0u, vq[1], src0);
      uint32_t x10 = __shfl_sync(~0u, vq[2], src0);
      uint32_t x11 = __shfl_sync(~0u, vq[3], src0);
      uint32_t x20 = __shfl_sync(~0u, vq[0], src1);
      uint32_t x21 = __shfl_sync(~0u, vq[1], src1);
      uint32_t x30 = __shfl_sync(~0u, vq[2], src1);
      uint32_t x31 = __shfl_sync(~0u, vq[3], src1);
      uint4 u = {odd ? x01 : x00, odd ? x11 : x10, odd ? x21 : x20,
                 odd ? x31 : x30};
      *(uint4*)&g_Q[qbase + ((size_t)(kcol * 8 + rc) * 32 + lane) * 4] = u;
    }
    // K: same shuffle pattern -> two STG.64 (rows g -> nc0, rows g+8 -> nc0+1)
    {
      uint32_t x00 = __shfl_sync(~0u, vk[0], src0);
      uint32_t x01 = __shfl_sync(~0u, vk[1], src0);
      uint32_t x10 = __shfl_sync(~0u, vk[2], src0);
      uint32_t x11 = __shfl_sync(~0u, vk[3], src0);
      uint32_t x20 = __shfl_sync(~0u, vk[0], src1);
      uint32_t x21 = __shfl_sync(~0u, vk[1], src1);
      uint32_t x30 = __shfl_sync(~0u, vk[2], src1);
      uint32_t x31 = __shfl_sync(~0u, vk[3], src1);
      uint2 u0 = {odd ? x01 : x00, odd ? x21 : x20};  // row g: k=t, k=t+4
      uint2 u1 = {odd ? x11 : x10, odd ? x31 : x30};  // row g+8
      *(uint2*)&g_K[kvb + ((size_t)(kcol * 4 + nc0) * 32 + lane) * 2] = u0;
      *(uint2*)&g_K[kvb + ((size_t)(kcol * 4 + nc0 + 1) * 32 + lane) * 2] = u1;
    }
    // V: transpose remap (dest lane d: gd=d>>2 is col&7, td=d&3 is k&3)
    {
      uint32_t y00 = __shfl_sync(~0u, vv[0], srcV0);
      uint32_t y01 = __shfl_sync(~0u, vv[1], srcV0);
      uint32_t y10 = __shfl_sync(~0u, vv[0], srcV1);
      uint32_t y11 = __shfl_sync(~0u, vv[1], srcV1);
      uint2 u0 = {selv ? y01 : y00, selv ? y11 : y10};
      uint32_t z00 = __shfl_sync(~0u, vv[2], srcV0);
      uint32_t z01 = __shfl_sync(~0u, vv[3], srcV0);
      uint32_t z10 = __shfl_sync(~0u, vv[2], srcV1);
      uint32_t z11 = __shfl_sync(~0u, vv[3], srcV1);
      uint2 u1 = {selv ? z01 : z00, selv ? z11 : z10};
      *(uint2*)&g_V[kvb + ((size_t)(nc0 * 8 + kcol) * 32 + lane) * 2] = u0;
      *(uint2*)&g_V[kvb + ((size_t)((nc0 + 1) * 8 + kcol) * 32 + lane) * 2] = u1;
    }
  }
}

// ---------------------------------------------------------------------------
// Kernel 2: causal flash attention. 256 thr, forced 2 blocks/SM. BN=64 KV
// stages. Each block runs two query tiles (qi = 15-a then a) -> 36 stages,
// one balanced wave of 256 blocks. One barrier per stage; P via quad shuffles.
// (Exact R12 structure — best measured configuration.)
// ---------------------------------------------------------------------------
__global__ __launch_bounds__(256, 2) void attn_kernel() {
  extern __shared__ uint32_t sm[];
  uint32_t* Qs = sm;            // 8192: [kc 8][rc 8][lane][4]
  uint32_t* Ks = Qs + 8192;     // 2 bufs x 4096 (64 rows, two kt tiles)
  uint32_t* Vs = Ks + 8192;     // 2 bufs x 4096
  const int tid = threadIdx.x;
  const int wid = tid >> 5, lane = tid & 31;
  const int g = lane >> 2, t = lane & 3;
  const int mrow = wid * 16;
  const int bh = blockIdx.y;

  const uint32_t* Kg = g_K + (size_t)bh * 64 * 2048;
  const uint32_t* Vg = g_V + (size_t)bh * 64 * 2048;
  const int src0 = (lane & ~3) + (t >> 1);  // quad-shuffle sources for P
  const int src1 = src0 + 2;
  const bool odd = t & 1;

#pragma unroll 1
  for (int sub = 0; sub < 2; sub++) {
    const int qi = sub ? blockIdx.x : 15 - blockIdx.x;
    const int ntiles = 2 * qi + 2;  // 64-row stages
    if (sub) __syncthreads();       // Qs/bufs of sub 0 fully consumed

    const uint32_t* Qg = g_Q + (size_t)(bh * 16 + qi) * 8192;
#pragma unroll
    for (int r = 0; r < 8; r++) {
      int f = tid + 256 * r;
      cpa16(&Qs[f * 4], &Qg[f * 4]);
    }
#pragma unroll
    for (int r = 0; r < 4; r++) {
      int f = tid + 256 * r;
      cpa16(&Ks[f * 4], &Kg[f * 4]);
      cpa16(&Vs[f * 4], &Vg[f * 4]);
    }
    cp_commit();

    float m0 = -1e30f, m1 = -1e30f, l0 = 0.f, l1 = 0.f;
    float o[8][4] = {};
    const int qrow0 = qi * 128 + mrow + g;

    for (int j = 0; j < ntiles; j++) {
      cp_wait0();       // copies for stage j arrived
      __syncthreads();  // stage j visible to all; all warps done with j-1

      if (j + 1 < ntiles) {
        const int nb = (j + 1) & 1;
        const uint32_t* Kn = Kg + (size_t)(j + 1) * 4096;
        const uint32_t* Vn = Vg + (size_t)(j + 1) * 4096;
#pragma unroll
        for (int r = 0; r < 4; r++) {
          int f = tid + 256 * r;
          cpa16(&Ks[nb * 4096 + f * 4], &Kn[f * 4]);
          cpa16(&Vs[nb * 4096 + f * 4], &Vn[f * 4]);
        }
        cp_commit();
      }

      const uint32_t* Kb = Ks + (j & 1) * 4096;
      const uint32_t* Vb = Vs + (j & 1) * 4096;

      // S = Q @ K^T  (128 x 64 chunk). Q frags re-read per stage (LDS.128).
      float s[8][4] = {};
#pragma unroll
      for (int kc = 0; kc < 8; kc++) {
        uint4 q4 = *(const uint4*)&Qs[((kc * 8 + wid) * 32 + lane) * 4];
#pragma unroll
        for (int n = 0; n < 8; n++) {
          uint2 kb = *(const uint2*)&Kb[((n >> 2) * 2048 +
                                         ((kc * 4 + (n & 3)) * 32 + lane) * 2)];
          mma_tf32(s[n], q4.x, q4.y, q4.z, q4.w, kb.x, kb.y);
        }
      }

      if (j >= 2 * qi) {  // only the last two stages can clip
#pragma unroll
        for (int n = 0; n < 8; n++)
#pragma unroll
          for (int i = 0; i < 4; i++) {
            int col = j * 64 + n * 8 + 2 * t + (i & 1);
            int row = qrow0 + ((i >= 2) ? 8 : 0);
            if (col > row) s[n][i] = -1e30f;
          }
      }

      // online softmax (log2 domain), rows warp-local, quad reduce
      float rmax0 = -1e30f, rmax1 = -1e30f;
#pragma unroll
      for (int n = 0; n < 8; n++) {
        rmax0 = fmaxf(rmax0, fmaxf(s[n][0], s[n][1]));
        rmax1 = fmaxf(rmax1, fmaxf(s[n][2], s[n][3]));
      }
      rmax0 = fmaxf(rmax0, __shfl_xor_sync(0xffffffffu, rmax0, 1));
      rmax0 = fmaxf(rmax0, __shfl_xor_sync(0xffffffffu, rmax0, 2));
      rmax1 = fmaxf(rmax1, __shfl_xor_sync(0xffffffffu, rmax1, 1));
      rmax1 = fmaxf(rmax1, __shfl_xor_sync(0xffffffffu, rmax1, 2));

      float nm0 = fmaxf(m0, rmax0), nm1 = fmaxf(m1, rmax1);
      float sc0 = ex2(m0 - nm0), sc1 = ex2(m1 - nm1);
      m0 = nm0;
      m1 = nm1;
#pragma unroll
      for (int n = 0; n < 8; n++) {
        o[n][0] *= sc0;
        o[n][1] *= sc0;
        o[n][2] *= sc1;
        o[n][3] *= sc1;
      }

      // Interleaved: per k-chunk, build P (ex2 + quad shuffles) then its 8 PV
      // MMAs; ex2 of chunk kc+1 overlaps the tensor pipe on chunk kc.
      float rs0 = 0.f, rs1 = 0.f;
#pragma unroll
      for (int kc = 0; kc < 8; kc++) {
        float p0 = __uint_as_float(f2tf(ex2(s[kc][0] - nm0)));
        float p1 = __uint_as_float(f2tf(ex2(s[kc][1] - nm0)));
        float p2 = __uint_as_float(f2tf(ex2(s[kc][2] - nm1)));
        float p3 = __uint_as_float(f2tf(ex2(s[kc][3] - nm1)));
        rs0 += p0;
        rs0 += p1;
        rs1 += p2;
        rs1 += p3;
        float x00 = __shfl_sync(0xffffffffu, p0, src0);
        float x01 = __shfl_sync(0xffffffffu, p1, src0);
        float x20 = __shfl_sync(0xffffffffu, p0, src1);
        float x21 = __shfl_sync(0xffffffffu, p1, src1);
        float x10 = __shfl_sync(0xffffffffu, p2, src0);
        float x11 = __shfl_sync(0xffffffffu, p3, src0);
        float x30 = __shfl_sync(0xffffffffu, p2, src1);
        float x31 = __shfl_sync(0xffffffffu, p3, src1);
        uint32_t a0 = __float_as_uint(odd ? x01 : x00);
        uint32_t a2 = __float_as_uint(odd ? x21 : x20);
        uint32_t a1 = __float_as_uint(odd ? x11 : x10);
        uint32_t a3 = __float_as_uint(odd ? x31 : x30);
#pragma unroll
        for (int nt = 0; nt < 8; nt++) {
          uint2 vb = *(const uint2*)&Vb[((kc * 8 + nt) * 32 + lane) * 2];
          mma_tf32(o[nt], a0, a1, a2, a3, vb.x, vb.y);
        }
      }
      rs0 += __shfl_xor_sync(0xffffffffu, rs0, 1);
      rs0 += __shfl_xor_sync(0xffffffffu, rs0, 2);
      rs1 += __shfl_xor_sync(0xffffffffu, rs1, 1);
      rs1 += __shfl_xor_sync(0xffffffffu, rs1, 2);
      l0 = l0 * sc0 + rs0;
      l1 = l1 * sc1 + rs1;
    }

    const int b = bh >> 4, h = bh & 15;
    float inv0 = 1.f / l0, inv1 = 1.f / l1;
#pragma unroll
    for (int nt = 0; nt < 8; nt++)
#pragma unroll
      for (int i = 0; i < 4; i++) {
        int srow = qi * 128 + mrow + g + ((i >= 2) ? 8 : 0);
        int col = nt * 8 + 2 * t + (i & 1);
        int row = b * PS + srow;  // logical Y row
        int e = h * PHD + col;    // logical Y col
        size_t yi_ = (size_t)(row >> 7) * 131072 + (size_t)(e >> 3) * 1024 +
                     aidx(row & 127, e & 7, 8);
        g_Y[yi_] = f2tf(o[nt][i] * ((i >= 2) ? inv1 : inv0));
      }
  }
}

// ---------------------------------------------------------------------------
// Kernel 3: output projection. 128x128 tile/block, 256 thr, 32-deep K stages
// double-buffered, ONE barrier per stage (exact R12 structure). Forced to
// 3 blocks/SM (reg cap 85) to add latency-hiding warps on the tensor pipe.
// ---------------------------------------------------------------------------
__global__ __launch_bounds__(256, 3) void proj_kernel(
    const float* __restrict__ bias, float* __restrict__ out) {
  extern __shared__ uint32_t sm[];
  uint32_t* Ys = sm;            // 2 x 4096: [kc 4][rc 8][lane][4]
  uint32_t* Ws = Ys + 8192;     // 2 x 4096: [kc 4][nc 16][lane][2]
  const int tid = threadIdx.x;
  const int wid = tid >> 5, lane = tid & 31;
  const int g = lane >> 2, t = lane & 3;
  const int wm = wid & 3, wn = wid >> 2;  // 4(m) x 2(n)
  const int bm = blockIdx.y, bn = blockIdx.x;

  const uint32_t* Yg = g_Y + (size_t)bm * 131072;
  const uint32_t* Wg = g_Wp + (size_t)bn * 131072;

#pragma unroll
  for (int r = 0; r < 4; r++) {
    int f = tid + 256 * r;
    cpa16(&Ys[f * 4], &Yg[f * 4]);
    cpa16(&Ws[f * 4], &Wg[f * 4]);
  }
  cp_commit();

  float acc[2][8][4] = {};
  const int NK = PE / 32;
  for (int kt = 0; kt < NK; kt++) {
    cp_wait0();
    __syncthreads();  // stage kt visible; all warps done with kt-1

    if (kt + 1 < NK) {  // prefetch into slot freed at kt-1
      const int nb = (kt + 1) & 1;
      const uint32_t* Yn = Yg + (size_t)(kt + 1) * 4096;
      const uint32_t* Wn = Wg + (size_t)(kt + 1) * 4096;
#pragma unroll
      for (int r = 0; r < 4; r++) {
        int f = tid + 256 * r;
        cpa16(&Ys[nb * 4096 + f * 4], &Yn[f * 4]);
        cpa16(&Ws[nb * 4096 + f * 4], &Wn[f * 4]);
      }
      cp_commit();
    }

    const uint32_t* Yb = Ys + (kt & 1) * 4096;
    const uint32_t* Wb = Ws + (kt & 1) * 4096;
#pragma unroll
    for (int kc = 0; kc < 4; kc++) {
      uint4 a[2];
#pragma unroll
      for (int mf = 0; mf < 2; mf++)
        a[mf] = *(const uint4*)&Yb[((kc * 8 + wm * 2 + mf) * 32 + lane) * 4];
#pragma unroll
      for (int nt = 0; nt < 8; nt++) {
        uint2 b2 = *(const uint2*)&Wb[((kc * 16 + wn * 8 + nt) * 32 + lane) * 2];
        mma_tf32(acc[0][nt], a[0].x, a[0].y, a[0].z, a[0].w, b2.x, b2.y);
        mma_tf32(acc[1][nt], a[1].x, a[1].y, a[1].z, a[1].w, b2.x, b2.y);
      }
    }
  }

#pragma unroll
  for (int mf = 0; mf < 2; mf++)
#pragma unroll
    for (int nt = 0; nt < 8; nt++) {
      int col = bn * 128 + wn * 64 + nt * 8 + 2 * t;
      int row0 = bm * 128 + wm * 32 + mf * 16 + g;
      float2 v0 = {acc[mf][nt][0] + bias[col], acc[mf][nt][1] + bias[col + 1]};
      float2 v1 = {acc[mf][nt][2] + bias[col], acc[mf][nt][3] + bias[col + 1]};
      *(float2*)&out[(size_t)row0 * PE + col] = v0;
      *(float2*)&out[(size_t)(row0 + 8) * PE + col] = v1;
    }
}

// ---------------------------------------------------------------------------
extern "C" void kernel_launch(void* const* d_in, const int* in_sizes, int n_in,
                              void* d_out, int out_size) {
  const float* x  = (const float*)d_in[0];
  const float* Wq = (const float*)d_in[1];
  const float* bq = (const float*)d_in[2];
  const float* Wk = (const float*)d_in[3];
  const float* bk = (const float*)d_in[4];
  const float* Wv = (const float*)d_in[5];
  const float* bv = (const float*)d_in[6];
  const float* Wp = (const float*)d_in[7];
  const float* bp = (const float*)d_in[8];
  float* out = (float*)d_out;

  const int smem_qkv  = (128 + 3 * 64) * PAD * 4;        // 87,040 B
  const int smem_attn = (8192 + 8192 + 8192) * 4;        // 98,304 B
  const int smem_proj = 16384 * 4;                       // 65,536 B
  cudaFuncSetAttribute(qkv_kernel, cudaFuncAttributeMaxDynamicSharedMemorySize, smem_qkv);
  cudaFuncSetAttribute(attn_kernel, cudaFuncAttributeMaxDynamicSharedMemorySize, smem_attn);
  cudaFuncSetAttribute(proj_kernel, cudaFuncAttributeMaxDynamicSharedMemorySize, smem_proj);

  qkv_kernel<<<512 + 256, 512, smem_qkv>>>(x, Wq, Wk, Wv, Wp, bq, bk, bv);
  attn_kernel<<<dim3(8, PB * PH), 256, smem_attn>>>();
  proj_kernel<<<dim3(PE / 128, (PB * PS) / 128), 256, smem_proj>>>(bp, out);
}

// round 16
// speedup vs baseline: 1.0905x; 1.0905x over previous
#include <cuda_runtime.h>
#include <cstdint>

#define PB 2
#define PS 2048
#define PE 1024
#define PH 16
#define PHD 64
#define MROWS (PB * PS * PH)
#define PAD 68   // qkv internal tiles

// Scratch, tf32 bit patterns (allocation-free rule).
// g_Q: A-frag layout  [bh][qt 16][kc 8][rc 8][lane 32][4]
// g_K: B-frag layout  [bh][kt 64][kc 8][nc 4][lane 32][2]
// g_V: B-frag layout  [bh][vt 64][kchunk 4][nc 8][lane 32][2]
// g_Y: A-frag layout  [mt 32][kc 128][rc 8][lane 32][4]
// g_Wp: B-frag layout [nt 8][kc 128][nc 16][lane 32][2]
__device__ uint32_t g_Q[(size_t)PB * PH * PS * PHD];
__device__ uint32_t g_K[(size_t)PB * PH * PS * PHD];
__device__ uint32_t g_V[(size_t)PB * PH * PS * PHD];
__device__ uint32_t g_Y[(size_t)PB * PS * PE];
__device__ uint32_t g_Wp[(size_t)PE * PE];

__device__ __forceinline__ uint32_t f2tf(float x) {
  uint32_t u;
  asm("cvt.rna.tf32.f32 %0, %1;" : "=r"(u) : "f"(x));
  return u;
}
__device__ __forceinline__ float ex2(float x) {
  float y;
  asm("ex2.approx.ftz.f32 %0, %1;" : "=f"(y) : "f"(x));
  return y;
}
__device__ __forceinline__ void mma_tf32(float c[4], uint32_t a0, uint32_t a1,
                                         uint32_t a2, uint32_t a3, uint32_t b0,
                                         uint32_t b1) {
  asm volatile(
      "mma.sync.aligned.m16n8k8.row.col.f32.tf32.tf32.f32 "
      "{%0,%1,%2,%3}, {%4,%5,%6,%7}, {%8,%9}, {%0,%1,%2,%3};"
      : "+f"(c[0]), "+f"(c[1]), "+f"(c[2]), "+f"(c[3])
      : "r"(a0), "r"(a1), "r"(a2), "r"(a3), "r"(b0), "r"(b1));
}
__device__ __forceinline__ void cpa16(uint32_t* smem_dst, const void* gsrc) {
  uint32_t d = (uint32_t)__cvta_generic_to_shared(smem_dst);
  asm volatile("cp.async.cg.shared.global [%0], [%1], 16;" ::"r"(d), "l"(gsrc));
}
__device__ __forceinline__ void cp_commit() {
  asm volatile("cp.async.commit_group;");
}
__device__ __forceinline__ void cp_wait0() {
  asm volatile("cp.async.wait_group 0;");
}

// A-frag index within one [kc][rc][lane][4] tile set, RCN row-chunks tall.
__device__ __forceinline__ size_t aidx(int row, int col, int RCN) {
  int rc = row >> 4, jlo = (row >> 3) & 1, g = row & 7;
  int kc = col >> 3, t = col & 3, hi = (col >> 2) & 1;
  return ((size_t)(kc * RCN + rc) * 32 + g * 4 + t) * 4 + hi * 2 + jlo;
}
// B-frag index within one [kc][nc][lane][2] tile set, NCN col-chunks wide.
__device__ __forceinline__ size_t bidx(int n, int k, int NCN) {
  int nc = n >> 3, g = n & 7;
  int kc = k >> 3, t = k & 3, hi = (k >> 2) & 1;
  return ((size_t)(kc * NCN + nc) * 32 + g * 4 + t) * 2 + hi;
}

// ---------------------------------------------------------------------------
// Kernel 1: fused QKV projection + (extra blocks) Wp fragment conversion.
// Compute blocks [0,512): bid = (bh 32, qt 16); 128 consecutive s of ONE head.
// Epilogue converts C-frags to A/B-frag register order via quad/cross-quad
// shuffles -> Q stored as STG.128, K/V as STG.64, all warp-contiguous.
// Blocks [512,768): convert Wp, 8 k per thread -> 2 contiguous STG.128.
// ---------------------------------------------------------------------------
__global__ __launch_bounds__(512) void qkv_kernel(
    const float* __restrict__ x,
    const float* __restrict__ Wq, const float* __restrict__ Wk,
    const float* __restrict__ Wv, const float* __restrict__ Wp,
    const float* __restrict__ bq, const float* __restrict__ bk,
    const float* __restrict__ bv) {
  const int tid = threadIdx.x;

  if (blockIdx.x >= 512) {  // Wp conversion: one n, 8 k per thread
    int p = (blockIdx.x - 512) * 512 + tid;  // 0..131071
    int n = p & 1023, kg = p >> 10;          // kg = k-chunk (8 wide)
    const float* src = &Wp[(size_t)n * 1024 + kg * 8];
    float4 w0 = *(const float4*)src;
    float4 w1 = *(const float4*)(src + 4);
    uint4 ua = {f2tf(w0.x), f2tf(w1.x), f2tf(w0.y), f2tf(w1.y)};
    uint4 ub = {f2tf(w0.z), f2tf(w1.z), f2tf(w0.w), f2tf(w1.w)};
    size_t o = (size_t)(n >> 7) * 131072 + (size_t)kg * 1024 +
               ((n >> 3) & 15) * 64 + (n & 7) * 8;
    *(uint4*)&g_Wp[o] = ua;
    *(uint4*)&g_Wp[o + 4] = ub;
    return;
  }

  extern __shared__ uint32_t sm[];
  uint32_t* Xs = sm;               // 128*PAD
  uint32_t* Aq = Xs + 128 * PAD;   // 64*PAD each
  uint32_t* Ak = Aq + 64 * PAD;
  uint32_t* Av = Ak + 64 * PAD;
  const int qt = blockIdx.x & 15, bh = blockIdx.x >> 4;
  const int b = bh >> 4, h = bh & 15;
  const int s0 = qt * 128;

#pragma unroll
  for (int r = 0; r < 2; r++) {
    int f = tid + 512 * r;
    int row = f >> 4, col = (f & 15) * 4;
    float4 q4 = *(const float4*)&Wq[row * 64 + col];
    float4 k4 = *(const float4*)&Wk[row * 64 + col];
    float4 v4 = *(const float4*)&Wv[row * 64 + col];
    uint4 uq = {f2tf(q4.x), f2tf(q4.y), f2tf(q4.z), f2tf(q4.w)};
    uint4 uk = {f2tf(k4.x), f2tf(k4.y), f2tf(k4.z), f2tf(k4.w)};
    uint4 uv = {f2tf(v4.x), f2tf(v4.y), f2tf(v4.z), f2tf(v4.w)};
    *(uint4*)&Aq[row * PAD + col] = uq;
    *(uint4*)&Ak[row * PAD + col] = uk;
    *(uint4*)&Av[row * PAD + col] = uv;
  }
#pragma unroll
  for (int r = 0; r < 4; r++) {
    int f = tid + 512 * r;
    int row = f >> 4, col = (f & 15) * 4;
    size_t xoff = ((size_t)((b * PS + s0 + row) * PH + h)) * 64 + col;
    float4 v = *(const float4*)&x[xoff];
    uint4 u = {f2tf(v.x), f2tf(v.y), f2tf(v.z), f2tf(v.w)};
    *(uint4*)&Xs[row * PAD + col] = u;
  }
  __syncthreads();

  const int wid = tid >> 5, lane = tid & 31;
  const int g = lane >> 2, t = lane & 3;
  const int mrow = (wid & 7) * 16;
  const int wn = wid >> 3;

  float cq[4][4] = {}, ck[4][4] = {}, cv[4][4] = {};
#pragma unroll
  for (int k0 = 0; k0 < 64; k0 += 8) {
    uint32_t a0 = Xs[(mrow + g) * PAD + k0 + t];
    uint32_t a1 = Xs[(mrow + g + 8) * PAD + k0 + t];
    uint32_t a2 = Xs[(mrow + g) * PAD + k0 + t + 4];
    uint32_t a3 = Xs[(mrow + g + 8) * PAD + k0 + t + 4];
#pragma unroll
    for (int nt = 0; nt < 4; nt++) {
      int n0 = wn * 32 + nt * 8;
      mma_tf32(cq[nt], a0, a1, a2, a3, Aq[(n0 + g) * PAD + k0 + t],
               Aq[(n0 + g) * PAD + k0 + t + 4]);
      mma_tf32(ck[nt], a0, a1, a2, a3, Ak[(n0 + g) * PAD + k0 + t],
               Ak[(n0 + g) * PAD + k0 + t + 4]);
      mma_tf32(cv[nt], a0, a1, a2, a3, Av[(n0 + g) * PAD + k0 + t],
               Av[(n0 + g) * PAD + k0 + t + 4]);
    }
  }

  const float qscale = 0.125f * 1.4426950408889634f;  // 1/sqrt(64) * log2(e)
  const size_t qbase = (size_t)(bh * 16 + qt) * 8192;
  const size_t kvb = (size_t)(bh * 64 + qt * 4) * 2048 +
                     (size_t)(mrow >> 5) * 2048;  // this warp's 32-row kt tile
  const int rc = wid & 7;
  const int nc0 = (mrow & 31) >> 3;  // 0 or 2
  const int src0 = (lane & ~3) + (t >> 1), src1 = src0 + 2;
  const bool odd = t & 1;
  const int srcV0 = (lane & 3) * 4 + (lane >> 3);  // V cross-quad sources
  const int srcV1 = srcV0 + 16;
  const bool selv = (lane >> 2) & 1;

#pragma unroll
  for (int nt = 0; nt < 4; nt++) {
    const int kcol = wn * 4 + nt;  // k-chunk of cols kcol*8..+7
    uint32_t vq[4], vk[4], vv[4];
#pragma unroll
    for (int i = 0; i < 4; i++) {
      int col = kcol * 8 + 2 * t + (i & 1);
      vq[i] = f2tf((cq[nt][i] + bq[col]) * qscale);
      vk[i] = f2tf(ck[nt][i] + bk[col]);
      vv[i] = f2tf(cv[nt][i] + bv[col]);
    }
    // Q: C-frag -> A-frag via quad shuffles, one STG.128
    {
      uint32_t x00 = __shfl_sync(~0u, vq[0], src0);
      uint32_t x01 = __shfl_sync(~0u, vq[1], src0);
      uint32_t x10 = __shfl_sync(~0u, vq[2], src0);
      uint32_t x11 = __shfl_sync(~0u, vq[3], src0);
      uint32_t x20 = __shfl_sync(~0u, vq[0], src1);
      uint32_t x21 = __shfl_sync(~0u, vq[1], src1);
      uint32_t x30 = __shfl_sync(~0u, vq[2], src1);
      uint32_t x31 = __shfl_sync(~0u, vq[3], src1);
      uint4 u = {odd ? x01 : x00, odd ? x11 : x10, odd ? x21 : x20,
                 odd ? x31 : x30};
      *(uint4*)&g_Q[qbase + ((size_t)(kcol * 8 + rc) * 32 + lane) * 4] = u;
    }
    // K: same shuffle pattern -> two STG.64 (rows g -> nc0, rows g+8 -> nc0+1)
    {
      uint32_t x00 = __shfl_sync(~0u, vk[0], src0);
      uint32_t x01 = __shfl_sync(~0u, vk[1], src0);
      uint32_t x10 = __shfl_sync(~0u, vk[2], src0);
      uint32_t x11 = __shfl_sync(~0u, vk[3], src0);
      uint32_t x20 = __shfl_sync(~0u, vk[0], src1);
      uint32_t x21 = __shfl_sync(~0u, vk[1], src1);
      uint32_t x30 = __shfl_sync(~0u, vk[2], src1);
      uint32_t x31 = __shfl_sync(~0u, vk[3], src1);
      uint2 u0 = {odd ? x01 : x00, odd ? x21 : x20};  // row g: k=t, k=t+4
      uint2 u1 = {odd ? x11 : x10, odd ? x31 : x30};  // row g+8
      *(uint2*)&g_K[kvb + ((size_t)(kcol * 4 + nc0) * 32 + lane) * 2] = u0;
      *(uint2*)&g_K[kvb + ((size_t)(kcol * 4 + nc0 + 1) * 32 + lane) * 2] = u1;
    }
    // V: transpose remap (dest lane d: gd=d>>2 is col&7, td=d&3 is k&3)
    {
      uint32_t y00 = __shfl_sync(~0u, vv[0], srcV0);
      uint32_t y01 = __shfl_sync(~0u, vv[1], srcV0);
      uint32_t y10 = __shfl_sync(~0u, vv[0], srcV1);
      uint32_t y11 = __shfl_sync(~0u, vv[1], srcV1);
      uint2 u0 = {selv ? y01 : y00, selv ? y11 : y10};
      uint32_t z00 = __shfl_sync(~0u, vv[2], srcV0);
      uint32_t z01 = __shfl_sync(~0u, vv[3], srcV0);
      uint32_t z10 = __shfl_sync(~0u, vv[2], srcV1);
      uint32_t z11 = __shfl_sync(~0u, vv[3], srcV1);
      uint2 u1 = {selv ? z01 : z00, selv ? z11 : z10};
      *(uint2*)&g_V[kvb + ((size_t)(nc0 * 8 + kcol) * 32 + lane) * 2] = u0;
      *(uint2*)&g_V[kvb + ((size_t)((nc0 + 1) * 8 + kcol) * 32 + lane) * 2] = u1;
    }
  }
}

// ---------------------------------------------------------------------------
// Kernel 2: causal flash attention. 256 thr, forced 2 blocks/SM. BN=64 KV
// stages. Each block runs two query tiles (qi = 15-a then a) -> 36 stages,
// one balanced wave of 256 blocks. One barrier per stage; P via quad shuffles.
// ---------------------------------------------------------------------------
__global__ __launch_bounds__(256, 2) void attn_kernel() {
  extern __shared__ uint32_t sm[];
  uint32_t* Qs = sm;            // 8192: [kc 8][rc 8][lane][4]
  uint32_t* Ks = Qs + 8192;     // 2 bufs x 4096 (64 rows, two kt tiles)
  uint32_t* Vs = Ks + 8192;     // 2 bufs x 4096
  const int tid = threadIdx.x;
  const int wid = tid >> 5, lane = tid & 31;
  const int g = lane >> 2, t = lane & 3;
  const int mrow = wid * 16;
  const int bh = blockIdx.y;

  const uint32_t* Kg = g_K + (size_t)bh * 64 * 2048;
  const uint32_t* Vg = g_V + (size_t)bh * 64 * 2048;
  const int src0 = (lane & ~3) + (t >> 1);  // quad-shuffle sources for P
  const int src1 = src0 + 2;
  const bool odd = t & 1;

#pragma unroll 1
  for (int sub = 0; sub < 2; sub++) {
    const int qi = sub ? blockIdx.x : 15 - blockIdx.x;
    const int ntiles = 2 * qi + 2;  // 64-row stages
    if (sub) __syncthreads();       // Qs/bufs of sub 0 fully consumed

    const uint32_t* Qg = g_Q + (size_t)(bh * 16 + qi) * 8192;
#pragma unroll
    for (int r = 0; r < 8; r++) {
      int f = tid + 256 * r;
      cpa16(&Qs[f * 4], &Qg[f * 4]);
    }
#pragma unroll
    for (int r = 0; r < 4; r++) {
      int f = tid + 256 * r;
      cpa16(&Ks[f * 4], &Kg[f * 4]);
      cpa16(&Vs[f * 4], &Vg[f * 4]);
    }
    cp_commit();

    float m0 = -1e30f, m1 = -1e30f, l0 = 0.f, l1 = 0.f;
    float o[8][4] = {};
    const int qrow0 = qi * 128 + mrow + g;

    for (int j = 0; j < ntiles; j++) {
      cp_wait0();       // copies for stage j arrived
      __syncthreads();  // stage j visible to all; all warps done with j-1

      if (j + 1 < ntiles) {
        const int nb = (j + 1) & 1;
        const uint32_t* Kn = Kg + (size_t)(j + 1) * 4096;
        const uint32_t* Vn = Vg + (size_t)(j + 1) * 4096;
#pragma unroll
        for (int r = 0; r < 4; r++) {
          int f = tid + 256 * r;
          cpa16(&Ks[nb * 4096 + f * 4], &Kn[f * 4]);
          cpa16(&Vs[nb * 4096 + f * 4], &Vn[f * 4]);
        }
        cp_commit();
      }

      const uint32_t* Kb = Ks + (j & 1) * 4096;
      const uint32_t* Vb = Vs + (j & 1) * 4096;

      // S = Q @ K^T  (128 x 64 chunk). Q frags re-read per stage (LDS.128).
      float s[8][4] = {};
#pragma unroll
      for (int kc = 0; kc < 8; kc++) {
        uint4 q4 = *(const uint4*)&Qs[((kc * 8 + wid) * 32 + lane) * 4];
#pragma unroll
        for (int n = 0; n < 8; n++) {
          uint2 kb = *(const uint2*)&Kb[((n >> 2) * 2048 +
                                         ((kc * 4 + (n & 3)) * 32 + lane) * 2)];
          mma_tf32(s[n], q4.x, q4.y, q4.z, q4.w, kb.x, kb.y);
        }
      }

      if (j >= 2 * qi) {  // only the last two stages can clip
#pragma unroll
        for (int n = 0; n < 8; n++)
#pragma unroll
          for (int i = 0; i < 4; i++) {
            int col = j * 64 + n * 8 + 2 * t + (i & 1);
            int row = qrow0 + ((i >= 2) ? 8 : 0);
            if (col > row) s[n][i] = -1e30f;
          }
      }

      // online softmax (log2 domain), rows warp-local, quad reduce
      float rmax0 = -1e30f, rmax1 = -1e30f;
#pragma unroll
      for (int n = 0; n < 8; n++) {
        rmax0 = fmaxf(rmax0, fmaxf(s[n][0], s[n][1]));
        rmax1 = fmaxf(rmax1, fmaxf(s[n][2], s[n][3]));
      }
      rmax0 = fmaxf(rmax0, __shfl_xor_sync(0xffffffffu, rmax0, 1));
      rmax0 = fmaxf(rmax0, __shfl_xor_sync(0xffffffffu, rmax0, 2));
      rmax1 = fmaxf(rmax1, __shfl_xor_sync(0xffffffffu, rmax1, 1));
      rmax1 = fmaxf(rmax1, __shfl_xor_sync(0xffffffffu, rmax1, 2));

      float nm0 = fmaxf(m0, rmax0), nm1 = fmaxf(m1, rmax1);
      float sc0 = ex2(m0 - nm0), sc1 = ex2(m1 - nm1);
      m0 = nm0;
      m1 = nm1;
#pragma unroll
      for (int n = 0; n < 8; n++) {
        o[n][0] *= sc0;
        o[n][1] *= sc0;
        o[n][2] *= sc1;
        o[n][3] *= sc1;
      }

      // Interleaved: per k-chunk, build P (ex2 + quad shuffles) then its 8 PV
      // MMAs; ex2 of chunk kc+1 overlaps the tensor pipe on chunk kc.
      float rs0 = 0.f, rs1 = 0.f;
#pragma unroll
      for (int kc = 0; kc < 8; kc++) {
        float p0 = __uint_as_float(f2tf(ex2(s[kc][0] - nm0)));
        float p1 = __uint_as_float(f2tf(ex2(s[kc][1] - nm0)));
        float p2 = __uint_as_float(f2tf(ex2(s[kc][2] - nm1)));
        float p3 = __uint_as_float(f2tf(ex2(s[kc][3] - nm1)));
        rs0 += p0;
        rs0 += p1;
        rs1 += p2;
        rs1 += p3;
        float x00 = __shfl_sync(0xffffffffu, p0, src0);
        float x01 = __shfl_sync(0xffffffffu, p1, src0);
        float x20 = __shfl_sync(0xffffffffu, p0, src1);
        float x21 = __shfl_sync(0xffffffffu, p1, src1);
        float x10 = __shfl_sync(0xffffffffu, p2, src0);
        float x11 = __shfl_sync(0xffffffffu, p3, src0);
        float x30 = __shfl_sync(0xffffffffu, p2, src1);
        float x31 = __shfl_sync(0xffffffffu, p3, src1);
        uint32_t a0 = __float_as_uint(odd ? x01 : x00);
        uint32_t a2 = __float_as_uint(odd ? x21 : x20);
        uint32_t a1 = __float_as_uint(odd ? x11 : x10);
        uint32_t a3 = __float_as_uint(odd ? x31 : x30);
#pragma unroll
        for (int nt = 0; nt < 8; nt++) {
          uint2 vb = *(const uint2*)&Vb[((kc * 8 + nt) * 32 + lane) * 2];
          mma_tf32(o[nt], a0, a1, a2, a3, vb.x, vb.y);
        }
      }
      rs0 += __shfl_xor_sync(0xffffffffu, rs0, 1);
      rs0 += __shfl_xor_sync(0xffffffffu, rs0, 2);
      rs1 += __shfl_xor_sync(0xffffffffu, rs1, 1);
      rs1 += __shfl_xor_sync(0xffffffffu, rs1, 2);
      l0 = l0 * sc0 + rs0;
      l1 = l1 * sc1 + rs1;
    }

    const int b = bh >> 4, h = bh & 15;
    float inv0 = 1.f / l0, inv1 = 1.f / l1;
#pragma unroll
    for (int nt = 0; nt < 8; nt++)
#pragma unroll
      for (int i = 0; i < 4; i++) {
        int srow = qi * 128 + mrow + g + ((i >= 2) ? 8 : 0);
        int col = nt * 8 + 2 * t + (i & 1);
        int row = b * PS + srow;  // logical Y row
        int e = h * PHD + col;    // logical Y col
        size_t yi_ = (size_t)(row >> 7) * 131072 + (size_t)(e >> 3) * 1024 +
                     aidx(row & 127, e & 7, 8);
        g_Y[yi_] = f2tf(o[nt][i] * ((i >= 2) ? inv1 : inv0));
      }
  }
}

// ---------------------------------------------------------------------------
// Kernel 3: output projection. 128x128 tile/block, 256 thr, 32-deep K stages
// double-buffered, ONE barrier per stage. A via LDS.128, B via LDS.64.
// ---------------------------------------------------------------------------
__global__ __launch_bounds__(256) void proj_kernel(
    const float* __restrict__ bias, float* __restrict__ out) {
  extern __shared__ uint32_t sm[];
  uint32_t* Ys = sm;            // 2 x 4096: [kc 4][rc 8][lane][4]
  uint32_t* Ws = Ys + 8192;     // 2 x 4096: [kc 4][nc 16][lane][2]
  const int tid = threadIdx.x;
  const int wid = tid >> 5, lane = tid & 31;
  const int g = lane >> 2, t = lane & 3;
  const int wm = wid & 3, wn = wid >> 2;  // 4(m) x 2(n)
  const int bm = blockIdx.y, bn = blockIdx.x;

  const uint32_t* Yg = g_Y + (size_t)bm * 131072;
  const uint32_t* Wg = g_Wp + (size_t)bn * 131072;

#pragma unroll
  for (int r = 0; r < 4; r++) {
    int f = tid + 256 * r;
    cpa16(&Ys[f * 4], &Yg[f * 4]);
    cpa16(&Ws[f * 4], &Wg[f * 4]);
  }
  cp_commit();

  float acc[2][8][4] = {};
  const int NK = PE / 32;
  for (int kt = 0; kt < NK; kt++) {
    cp_wait0();
    __syncthreads();  // stage kt visible; all warps done with kt-1

    if (kt + 1 < NK) {  // prefetch into slot freed at kt-1
      const int nb = (kt + 1) & 1;
      const uint32_t* Yn = Yg + (size_t)(kt + 1) * 4096;
      const uint32_t* Wn = Wg + (size_t)(kt + 1) * 4096;
#pragma unroll
      for (int r = 0; r < 4; r++) {
        int f = tid + 256 * r;
        cpa16(&Ys[nb * 4096 + f * 4], &Yn[f * 4]);
        cpa16(&Ws[nb * 4096 + f * 4], &Wn[f * 4]);
      }
      cp_commit();
    }

    const uint32_t* Yb = Ys + (kt & 1) * 4096;
    const uint32_t* Wb = Ws + (kt & 1) * 4096;
#pragma unroll
    for (int kc = 0; kc < 4; kc++) {
      uint4 a[2];
#pragma unroll
      for (int mf = 0; mf < 2; mf++)
        a[mf] = *(const uint4*)&Yb[((kc * 8 + wm * 2 + mf) * 32 + lane) * 4];
#pragma unroll
      for (int nt = 0; nt < 8; nt++) {
        uint2 b2 = *(const uint2*)&Wb[((kc * 16 + wn * 8 + nt) * 32 + lane) * 2];
        mma_tf32(acc[0][nt], a[0].x, a[0].y, a[0].z, a[0].w, b2.x, b2.y);
        mma_tf32(acc[1][nt], a[1].x, a[1].y, a[1].z, a[1].w, b2.x, b2.y);
      }
    }
  }

#pragma unroll
  for (int mf = 0; mf < 2; mf++)
#pragma unroll
    for (int nt = 0; nt < 8; nt++) {
      int col = bn * 128 + wn * 64 + nt * 8 + 2 * t;
      int row0 = bm * 128 + wm * 32 + mf * 16 + g;
      float2 v0 = {acc[mf][nt][0] + bias[col], acc[mf][nt][1] + bias[col + 1]};
      float2 v1 = {acc[mf][nt][2] + bias[col], acc[mf][nt][3] + bias[col + 1]};
      *(float2*)&out[(size_t)row0 * PE + col] = v0;
      *(float2*)&out[(size_t)(row0 + 8) * PE + col] = v1;
    }
}

// ---------------------------------------------------------------------------
extern "C" void kernel_launch(void* const* d_in, const int* in_sizes, int n_in,
                              void* d_out, int out_size) {
  const float* x  = (const float*)d_in[0];
  const float* Wq = (const float*)d_in[1];
  const float* bq = (const float*)d_in[2];
  const float* Wk = (const float*)d_in[3];
  const float* bk = (const float*)d_in[4];
  const float* Wv = (const float*)d_in[5];
  const float* bv = (const float*)d_in[6];
  const float* Wp = (const float*)d_in[7];
  const float* bp = (const float*)d_in[8];
  float* out = (float*)d_out;

  const int smem_qkv  = (128 + 3 * 64) * PAD * 4;        // 87,040 B
  const int smem_attn = (8192 + 8192 + 8192) * 4;        // 98,304 B
  const int smem_proj = 16384 * 4;                       // 65,536 B
  cudaFuncSetAttribute(qkv_kernel, cudaFuncAttributeMaxDynamicSharedMemorySize, smem_qkv);
  cudaFuncSetAttribute(attn_kernel, cudaFuncAttributeMaxDynamicSharedMemorySize, smem_attn);
  cudaFuncSetAttribute(proj_kernel, cudaFuncAttributeMaxDynamicSharedMemorySize, smem_proj);

  qkv_kernel<<<512 + 256, 512, smem_qkv>>>(x, Wq, Wk, Wv, Wp, bq, bk, bv);
  attn_kernel<<<dim3(8, PB * PH), 256, smem_attn>>>();
  proj_kernel<<<dim3(PE / 128, (PB * PS) / 128), 256, smem_proj>>>(bp, out);
}